// round 1
// baseline (speedup 1.0000x reference)
#include <cuda_runtime.h>
#include <math.h>
#include <stdint.h>

#define BATCH 4
#define SEQ   2048
#define DIM   256
#define NHEAD 4
#define HDIM  64
#define NROWS (BATCH*NHEAD*SEQ)

// ---- scratch (allocation-free: device globals) ----
static __device__ float g_Q[BATCH*NHEAD*SEQ*HDIM];
static __device__ float g_K[BATCH*NHEAD*SEQ*HDIM];
static __device__ float g_V[BATCH*NHEAD*SEQ*HDIM];
static __device__ float g_scores[(size_t)NROWS * SEQ];   // 268 MB
static __device__ float g_att[BATCH*SEQ*DIM];
static __device__ float g_mixed[BATCH*SEQ*DIM];
static __device__ float g_xmean[BATCH*DIM];
static __device__ float g_gproj[BATCH*DIM];

// ---- order-preserving float<->uint key transform ----
__device__ __forceinline__ unsigned f2k(float f){
    unsigned u = __float_as_uint(f);
    return (u & 0x80000000u) ? ~u : (u | 0x80000000u);
}
__device__ __forceinline__ float k2f(unsigned k){
    return (k & 0x80000000u) ? __uint_as_float(k & 0x7fffffffu)
                             : __uint_as_float(~k);
}

// =====================================================================
// Generic fp32 GEMM:  C[M,N] = alpha * A[M,K] @ B[N,K]^T (+ bias[n])
// BM=128, BN=64, BK=16, 256 threads, 8x4 microtile.
// outMode==1 scatters C to [b,h,s,hd] layout (QKV head split).
// =====================================================================
__global__ void __launch_bounds__(256) gemm_tn_kernel(
    const float* __restrict__ A, const float* __restrict__ B,
    const float* __restrict__ bias, float* __restrict__ C,
    int M, int N, int K,
    size_t sA, size_t sB, size_t sC,
    float alpha, int outMode)
{
    __shared__ float As[16][132];
    __shared__ float Bs[16][68];
    const int z = blockIdx.z;
    A += (size_t)z * sA;
    B += (size_t)z * sB;
    C += (size_t)z * sC;

    const int tid = threadIdx.x;
    const int m0 = blockIdx.y * 128;
    const int n0 = blockIdx.x * 64;

    const int lr = tid >> 2;          // 0..63
    const int lc = (tid & 3) << 2;    // 0,4,8,12
    const int tm = (tid >> 4) << 3;   // 0..120
    const int tn = (tid & 15) << 2;   // 0..60

    float acc[8][4];
#pragma unroll
    for (int i = 0; i < 8; i++)
#pragma unroll
        for (int j = 0; j < 4; j++) acc[i][j] = 0.f;

    const float* Ap = A + (size_t)(m0 + lr) * K + lc;
    const float* Bp = B + (size_t)(n0 + lr) * K + lc;
    const size_t A64 = (size_t)64 * K;

    for (int k0 = 0; k0 < K; k0 += 16){
        float4 a0 = *(const float4*)(Ap + k0);
        float4 a1 = *(const float4*)(Ap + A64 + k0);
        float4 b0 = *(const float4*)(Bp + k0);
        __syncthreads();
        As[lc+0][lr]    = a0.x; As[lc+1][lr]    = a0.y;
        As[lc+2][lr]    = a0.z; As[lc+3][lr]    = a0.w;
        As[lc+0][lr+64] = a1.x; As[lc+1][lr+64] = a1.y;
        As[lc+2][lr+64] = a1.z; As[lc+3][lr+64] = a1.w;
        Bs[lc+0][lr] = b0.x; Bs[lc+1][lr] = b0.y;
        Bs[lc+2][lr] = b0.z; Bs[lc+3][lr] = b0.w;
        __syncthreads();
#pragma unroll
        for (int kk = 0; kk < 16; kk++){
            float4 aa0 = *(const float4*)&As[kk][tm];
            float4 aa1 = *(const float4*)&As[kk][tm + 4];
            float4 bb  = *(const float4*)&Bs[kk][tn];
            float av[8] = {aa0.x, aa0.y, aa0.z, aa0.w, aa1.x, aa1.y, aa1.z, aa1.w};
            float bv[4] = {bb.x, bb.y, bb.z, bb.w};
#pragma unroll
            for (int i = 0; i < 8; i++)
#pragma unroll
                for (int j = 0; j < 4; j++)
                    acc[i][j] = fmaf(av[i], bv[j], acc[i][j]);
        }
    }

#pragma unroll
    for (int i = 0; i < 8; i++){
        int m = m0 + tm + i;
#pragma unroll
        for (int j = 0; j < 4; j++){
            int n = n0 + tn + j;
            float v = acc[i][j] * alpha;
            if (bias) v += bias[n];
            if (outMode == 1){
                int b = m >> 11, s = m & 2047;
                int h = n >> 6,  hd = n & 63;
                C[(((size_t)b * NHEAD + h) * SEQ + s) * HDIM + hd] = v;
            } else {
                C[(size_t)m * N + n] = v;
            }
        }
    }
}

// =====================================================================
// xmean[b][d] = mean over seq of x[b][s][d]
// =====================================================================
__global__ void mean_kernel(const float* __restrict__ x, float* __restrict__ xmean)
{
    int b = blockIdx.x, d = threadIdx.x;
    const float* p = x + (size_t)b * SEQ * DIM + d;
    float s = 0.f;
    for (int i = 0; i < SEQ; i++) s += p[(size_t)i * DIM];
    xmean[b * DIM + d] = s * (1.0f / SEQ);
}

// =====================================================================
// gate: g = sigmoid(xmean @ Wg^T + bg); gproj = g @ Wgp^T + bgp
// =====================================================================
__global__ void gate_kernel(const float* __restrict__ xmean,
    const float* __restrict__ Wg, const float* __restrict__ bg,
    const float* __restrict__ Wgp, const float* __restrict__ bgp,
    float* __restrict__ gproj)
{
    __shared__ float gg[BATCH][16];
    int t = threadIdx.x;
    if (t < BATCH * 16){
        int b = t >> 4, j = t & 15;
        const float* xm = xmean + b * DIM;
        const float* w  = Wg + j * DIM;
        float s = bg[j];
        for (int d = 0; d < DIM; d++) s = fmaf(xm[d], w[d], s);
        gg[b][j] = 1.f / (1.f + expf(-s));
    }
    __syncthreads();
    for (int idx = t; idx < BATCH * DIM; idx += 256){
        int b = idx >> 8, d = idx & 255;
        const float* w = Wgp + d * 16;
        float s = bgp[d];
#pragma unroll
        for (int j = 0; j < 16; j++) s = fmaf(gg[b][j], w[j], s);
        gproj[idx] = s;
    }
}

// =====================================================================
// exact k-th largest (1-indexed, counts duplicates) via 4-round radix
// select over 2048 keys in smem. Deterministic value result.
// =====================================================================
__device__ __forceinline__ unsigned radix_select(
    const unsigned* keys, int* hist, int* scan, int* s_bin, int t, int rank)
{
    unsigned prefix = 0;
    int rem = rank;
    for (int shift = 24; shift >= 0; shift -= 8){
        hist[t] = 0;
        __syncthreads();
        unsigned himask = (shift == 24) ? 0u : (0xFFFFFFFFu << (shift + 8));
#pragma unroll
        for (int i = 0; i < 8; i++){
            unsigned key = keys[t + (i << 8)];
            if ((key & himask) == prefix)
                atomicAdd(&hist[(key >> shift) & 0xFFu], 1);
        }
        __syncthreads();
        scan[t] = hist[t];
        __syncthreads();
        // inclusive suffix sum: scan[i] = sum(hist[i..255])
        for (int off = 1; off < 256; off <<= 1){
            int v = (t + off < 256) ? scan[t + off] : 0;
            __syncthreads();
            scan[t] += v;
            __syncthreads();
        }
        int nxt = (t < 255) ? scan[t + 1] : 0;
        if (scan[t] >= rem && nxt < rem) *s_bin = t;
        __syncthreads();
        int bin = *s_bin;
        rem -= (bin < 255) ? scan[bin + 1] : 0;
        prefix |= ((unsigned)bin) << shift;
        __syncthreads();
    }
    return prefix;
}

// =====================================================================
// per-row: quantile threshold -> masked softmax -> sparse att = p @ V
// one block per (b,h,q) row. Fully deterministic (no atomic ordering).
// =====================================================================
__global__ void __launch_bounds__(256) attn_row_kernel(
    const float* __restrict__ scores,
    const float* __restrict__ V,
    float* __restrict__ att)
{
    __shared__ unsigned keys[SEQ];
    __shared__ float pv[SEQ];
    __shared__ unsigned short idxs[SEQ];
    __shared__ int hist[256];
    __shared__ int scan[256];
    __shared__ float redbuf[8];
    __shared__ float accbuf[8][64];
    __shared__ int s_bin;
    __shared__ float s_max, s_sum;

    const int t  = threadIdx.x;
    const int r  = blockIdx.x;
    const int q  = r & (SEQ - 1);
    const int bh = r >> 11;

    const float* row = scores + (size_t)r * SEQ;
    float sv[8];
    float lmax = -3.4e38f;
#pragma unroll
    for (int i = 0; i < 8; i++){
        int k = t + (i << 8);
        float s = row[k];
        sv[i] = s;
        keys[k] = f2k(s);
        lmax = fmaxf(lmax, s);
    }
#pragma unroll
    for (int off = 16; off; off >>= 1)
        lmax = fmaxf(lmax, __shfl_xor_sync(0xffffffffu, lmax, off));
    if ((t & 31) == 0) redbuf[t >> 5] = lmax;
    __syncthreads();
    if (t == 0){
        float m = redbuf[0];
#pragma unroll
        for (int i = 1; i < 8; i++) m = fmaxf(m, redbuf[i]);
        s_max = m;
    }
    __syncthreads();

    // sorted ascending index 1842 = 206th largest, 1843 = 205th largest
    unsigned kHi = radix_select(keys, hist, scan, &s_bin, t, 205);
    unsigned kLo = radix_select(keys, hist, scan, &s_bin, t, 206);
    float shi = k2f(kHi), slo = k2f(kLo);
    const float idxf = 0.9f * 2047.0f;       // f32, matches jnp.quantile
    const float frac = idxf - 1842.0f;
    float thr = slo + frac * (shi - slo);
    float rowmax = s_max;

    // keep mask + exp, deterministic compaction via prefix scan
    float ev[8];
    unsigned kmask = 0;
    int kcnt = 0;
    float lsum = 0.f;
#pragma unroll
    for (int i = 0; i < 8; i++){
        ev[i] = 0.f;
        if (sv[i] >= thr){
            float e = expf(sv[i] - rowmax);
            ev[i] = e; lsum += e;
            kmask |= (1u << i); kcnt++;
        }
    }
    scan[t] = kcnt;
    __syncthreads();
    for (int off = 1; off < 256; off <<= 1){
        int v = (t >= off) ? scan[t - off] : 0;
        __syncthreads();
        scan[t] += v;
        __syncthreads();
    }
    int total = scan[255];
    int pos = scan[t] - kcnt;
#pragma unroll
    for (int i = 0; i < 8; i++){
        if (kmask & (1u << i)){
            idxs[pos] = (unsigned short)(t + (i << 8));
            pv[pos] = ev[i];
            pos++;
        }
    }
#pragma unroll
    for (int off = 16; off; off >>= 1)
        lsum += __shfl_xor_sync(0xffffffffu, lsum, off);
    if ((t & 31) == 0) redbuf[t >> 5] = lsum;
    __syncthreads();                     // also publishes idxs/pv
    if (t == 0){
        float ss = 0.f;
#pragma unroll
        for (int i = 0; i < 8; i++) ss += redbuf[i];
        s_sum = ss;
    }
    __syncthreads();

    // sparse att: 8 warps gather V rows, lane covers hd and hd+32
    const int w = t >> 5, lane = t & 31;
    const float inv = 1.0f / s_sum;
    const float* Vh = V + (size_t)bh * SEQ * HDIM;
    float a0 = 0.f, a1 = 0.f;
    for (int j = w; j < total; j += 8){
        float p = pv[j];
        const float* vr = Vh + ((size_t)idxs[j] << 6);
        a0 += p * vr[lane];
        a1 += p * vr[lane + 32];
    }
    accbuf[w][lane]      = a0;
    accbuf[w][lane + 32] = a1;
    __syncthreads();
    if (t < 64){
        float tot = 0.f;
#pragma unroll
        for (int w2 = 0; w2 < 8; w2++) tot += accbuf[w2][t];
        int h = bh & (NHEAD - 1), b = bh >> 2;
        att[((size_t)b * SEQ + q) * DIM + h * HDIM + t] = tot * inv;
    }
}

// =====================================================================
// mixed = g * distill(att) + (1-g) * att ; distill = 16x16 per group
// =====================================================================
__global__ void mix_kernel(const float* __restrict__ att,
    const float* __restrict__ Wd, const float* __restrict__ bd,
    const float* __restrict__ gproj, float* __restrict__ mixed)
{
    __shared__ float arow[DIM];
    __shared__ float wd[256];
    __shared__ float bds[16];
    int m = blockIdx.x;
    int b = m >> 11;
    int t = threadIdx.x;
    arow[t] = att[(size_t)m * DIM + t];
    wd[t] = Wd[t];
    if (t < 16) bds[t] = bd[t];
    __syncthreads();
    int g16 = (t >> 4) << 4;
    int jrow = t & 15;
    float s = bds[jrow];
#pragma unroll
    for (int j = 0; j < 16; j++)
        s = fmaf(arow[g16 + j], wd[jrow * 16 + j], s);
    float g = gproj[b * DIM + t];
    mixed[(size_t)m * DIM + t] = g * s + (1.f - g) * arow[t];
}

// =====================================================================
extern "C" void kernel_launch(void* const* d_in, const int* in_sizes, int n_in,
                              void* d_out, int out_size)
{
    (void)in_sizes; (void)n_in; (void)out_size;
    const float* x   = (const float*)d_in[0];
    const float* Wq  = (const float*)d_in[1];
    const float* bq  = (const float*)d_in[2];
    const float* Wk  = (const float*)d_in[3];
    const float* bk  = (const float*)d_in[4];
    const float* Wv  = (const float*)d_in[5];
    const float* bv  = (const float*)d_in[6];
    const float* Wd  = (const float*)d_in[7];
    const float* bd  = (const float*)d_in[8];
    const float* Wg  = (const float*)d_in[9];
    const float* bg  = (const float*)d_in[10];
    const float* Wgp = (const float*)d_in[11];
    const float* bgp = (const float*)d_in[12];
    const float* Wo  = (const float*)d_in[13];
    const float* bo  = (const float*)d_in[14];
    float* out = (float*)d_out;

    float *pQ, *pK, *pV, *pS, *pAtt, *pMix, *pXm, *pGp;
    cudaGetSymbolAddress((void**)&pQ,   g_Q);
    cudaGetSymbolAddress((void**)&pK,   g_K);
    cudaGetSymbolAddress((void**)&pV,   g_V);
    cudaGetSymbolAddress((void**)&pS,   g_scores);
    cudaGetSymbolAddress((void**)&pAtt, g_att);
    cudaGetSymbolAddress((void**)&pMix, g_mixed);
    cudaGetSymbolAddress((void**)&pXm,  g_xmean);
    cudaGetSymbolAddress((void**)&pGp,  g_gproj);

    mean_kernel<<<BATCH, DIM>>>(x, pXm);
    gate_kernel<<<1, 256>>>(pXm, Wg, bg, Wgp, bgp, pGp);

    dim3 gq(DIM / 64, (BATCH * SEQ) / 128, 1);
    gemm_tn_kernel<<<gq, 256>>>(x, Wq, bq, pQ, BATCH*SEQ, DIM, DIM, 0, 0, 0, 1.f, 1);
    gemm_tn_kernel<<<gq, 256>>>(x, Wk, bk, pK, BATCH*SEQ, DIM, DIM, 0, 0, 0, 1.f, 1);
    gemm_tn_kernel<<<gq, 256>>>(x, Wv, bv, pV, BATCH*SEQ, DIM, DIM, 0, 0, 0, 1.f, 1);

    dim3 gs(SEQ / 64, SEQ / 128, BATCH * NHEAD);
    gemm_tn_kernel<<<gs, 256>>>(pQ, pK, nullptr, pS, SEQ, SEQ, HDIM,
                                (size_t)SEQ * HDIM, (size_t)SEQ * HDIM,
                                (size_t)SEQ * SEQ, 0.125f, 0);

    attn_row_kernel<<<NROWS, 256>>>(pS, pV, pAtt);
    mix_kernel<<<BATCH * SEQ, 256>>>(pAtt, Wd, bd, pGp, pMix);

    gemm_tn_kernel<<<gq, 256>>>(pMix, Wo, bo, out, BATCH*SEQ, DIM, DIM, 0, 0, 0, 1.f, 0);
}

// round 2
// speedup vs baseline: 2.3257x; 2.3257x over previous
#include <cuda_runtime.h>
#include <math.h>
#include <stdint.h>

#define BATCH 4
#define SEQ   2048
#define DIM   256
#define NHEAD 4
#define HDIM  64
#define NROWS (BATCH*NHEAD*SEQ)

// ---- scratch (allocation-free: device globals) ----
static __device__ float g_Q[BATCH*NHEAD*SEQ*HDIM];
static __device__ float g_K[BATCH*NHEAD*SEQ*HDIM];
static __device__ float g_V[BATCH*NHEAD*SEQ*HDIM];
static __device__ float g_scores[(size_t)NROWS * SEQ];   // 268 MB
static __device__ float g_att[BATCH*SEQ*DIM];
static __device__ float g_mixed[BATCH*SEQ*DIM];
static __device__ float g_xmean[BATCH*DIM];
static __device__ float g_gproj[BATCH*DIM];
static __device__ float g_mpart[BATCH*16*DIM];

// ---- order-preserving float<->uint key transform ----
__device__ __forceinline__ unsigned f2k(float f){
    unsigned u = __float_as_uint(f);
    return (u & 0x80000000u) ? ~u : (u | 0x80000000u);
}
__device__ __forceinline__ float k2f(unsigned k){
    return (k & 0x80000000u) ? __uint_as_float(k & 0x7fffffffu)
                             : __uint_as_float(~k);
}

// =====================================================================
// 128x128 SGEMM tile body: C = alpha * A[M,K] @ B[N,K]^T (+bias)
// BK=32, 256 threads, 8x8 microtile (split 4+4 at +64 offsets),
// k-major smem with pad 132 (conflict-free v4 loads), reg prefetch.
// mode 1 scatters output to [b,h,s,hd] (QKV head split).
// =====================================================================
__device__ __forceinline__ void gemm_tile(
    const float* __restrict__ A, const float* __restrict__ B,
    const float* __restrict__ bias, float* __restrict__ C,
    int K, int N, float alpha, int m0, int n0, int mode)
{
    __shared__ float As[32][132];
    __shared__ float Bs[32][132];
    const int tid = threadIdx.x;
    const int tx = tid & 15, ty = tid >> 4;
    const int lm = tid >> 1;
    const int lk4 = tid & 1;

    const float* Ag = A + (size_t)(m0 + lm) * K + lk4 * 4;
    const float* Bg = B + (size_t)(n0 + lm) * K + lk4 * 4;

    float4 pa[4], pb[4];
#pragma unroll
    for (int kk = 0; kk < 4; kk++){
        pa[kk] = *(const float4*)(Ag + kk * 8);
        pb[kk] = *(const float4*)(Bg + kk * 8);
    }

    float acc[8][8];
#pragma unroll
    for (int i = 0; i < 8; i++)
#pragma unroll
        for (int j = 0; j < 8; j++) acc[i][j] = 0.f;

    int k0 = 0;
    for (;;){
        __syncthreads();
#pragma unroll
        for (int kk = 0; kk < 4; kk++){
            int kc = lk4 * 4 + kk * 8;
            As[kc+0][lm] = pa[kk].x; As[kc+1][lm] = pa[kk].y;
            As[kc+2][lm] = pa[kk].z; As[kc+3][lm] = pa[kk].w;
            Bs[kc+0][lm] = pb[kk].x; Bs[kc+1][lm] = pb[kk].y;
            Bs[kc+2][lm] = pb[kk].z; Bs[kc+3][lm] = pb[kk].w;
        }
        __syncthreads();
        k0 += 32;
        if (k0 < K){
#pragma unroll
            for (int kk = 0; kk < 4; kk++){
                pa[kk] = *(const float4*)(Ag + k0 + kk * 8);
                pb[kk] = *(const float4*)(Bg + k0 + kk * 8);
            }
        }
#pragma unroll
        for (int kk = 0; kk < 32; kk++){
            float4 a0 = *(const float4*)&As[kk][ty * 4];
            float4 a1 = *(const float4*)&As[kk][64 + ty * 4];
            float4 b0 = *(const float4*)&Bs[kk][tx * 4];
            float4 b1 = *(const float4*)&Bs[kk][64 + tx * 4];
            float av[8] = {a0.x, a0.y, a0.z, a0.w, a1.x, a1.y, a1.z, a1.w};
            float bv[8] = {b0.x, b0.y, b0.z, b0.w, b1.x, b1.y, b1.z, b1.w};
#pragma unroll
            for (int i = 0; i < 8; i++)
#pragma unroll
                for (int j = 0; j < 8; j++)
                    acc[i][j] = fmaf(av[i], bv[j], acc[i][j]);
        }
        if (k0 >= K) break;
    }

    // epilogue
    float bvals[8];
#pragma unroll
    for (int jj = 0; jj < 2; jj++){
        int c = n0 + jj * 64 + tx * 4;
        if (bias){
            float4 bb = *(const float4*)(bias + c);
            bvals[jj*4+0] = bb.x; bvals[jj*4+1] = bb.y;
            bvals[jj*4+2] = bb.z; bvals[jj*4+3] = bb.w;
        } else {
            bvals[jj*4+0] = bvals[jj*4+1] = bvals[jj*4+2] = bvals[jj*4+3] = 0.f;
        }
    }
#pragma unroll
    for (int ii = 0; ii < 8; ii++){
        int r = m0 + ((ii < 4) ? (ty * 4 + ii) : (64 + ty * 4 + ii - 4));
#pragma unroll
        for (int jj = 0; jj < 2; jj++){
            int c = n0 + jj * 64 + tx * 4;
            float4 v;
            v.x = fmaf(acc[ii][jj*4+0], alpha, bvals[jj*4+0]);
            v.y = fmaf(acc[ii][jj*4+1], alpha, bvals[jj*4+1]);
            v.z = fmaf(acc[ii][jj*4+2], alpha, bvals[jj*4+2]);
            v.w = fmaf(acc[ii][jj*4+3], alpha, bvals[jj*4+3]);
            if (mode == 0){
                *(float4*)(C + (size_t)r * N + c) = v;
            } else {
                int b = r >> 11, s = r & 2047;
                int h = c >> 6,  hd = c & 63;
                *(float4*)(C + (((size_t)(b * NHEAD + h) * SEQ + s) << 6) + hd) = v;
            }
        }
    }
}

__global__ void __launch_bounds__(256, 2) qkv_kernel(
    const float* __restrict__ x,
    const float* __restrict__ Wq, const float* __restrict__ bq,
    const float* __restrict__ Wk, const float* __restrict__ bk,
    const float* __restrict__ Wv, const float* __restrict__ bv,
    float* Q, float* Kp, float* Vp)
{
    int z = blockIdx.z;
    const float* W = (z == 0) ? Wq : ((z == 1) ? Wk : Wv);
    const float* b = (z == 0) ? bq : ((z == 1) ? bk : bv);
    float* O = (z == 0) ? Q : ((z == 1) ? Kp : Vp);
    gemm_tile(x, W, b, O, DIM, DIM, 1.f, blockIdx.y * 128, blockIdx.x * 128, 1);
}

__global__ void __launch_bounds__(256, 2) gemm_kernel(
    const float* __restrict__ A, const float* __restrict__ B,
    const float* __restrict__ bias, float* __restrict__ C,
    int K, int N, float alpha, size_t sA, size_t sB, size_t sC)
{
    int z = blockIdx.z;
    gemm_tile(A + (size_t)z * sA, B + (size_t)z * sB, bias, C + (size_t)z * sC,
              K, N, alpha, blockIdx.y * 128, blockIdx.x * 128, 0);
}

// =====================================================================
// two-stage mean over seq
// =====================================================================
__global__ void mean1_kernel(const float* __restrict__ x, float* __restrict__ part)
{
    int b = blockIdx.x, c = blockIdx.y, t = threadIdx.x;
    const float* p = x + ((size_t)b * SEQ + c * 128) * DIM + t;
    float s = 0.f;
    for (int i = 0; i < 128; i++) s += p[(size_t)i * DIM];
    part[(b * 16 + c) * DIM + t] = s;
}
__global__ void mean2_kernel(const float* __restrict__ part, float* __restrict__ xmean)
{
    int b = blockIdx.x, t = threadIdx.x;
    float s = 0.f;
#pragma unroll
    for (int i = 0; i < 16; i++) s += part[(b * 16 + i) * DIM + t];
    xmean[b * DIM + t] = s * (1.0f / SEQ);
}

// =====================================================================
// gate: g = sigmoid(xmean @ Wg^T + bg); gproj = g @ Wgp^T + bgp
// =====================================================================
__global__ void gate_kernel(const float* __restrict__ xmean,
    const float* __restrict__ Wg, const float* __restrict__ bg,
    const float* __restrict__ Wgp, const float* __restrict__ bgp,
    float* __restrict__ gproj)
{
    __shared__ float gg[BATCH][16];
    int t = threadIdx.x;
    if (t < BATCH * 16){
        int b = t >> 4, j = t & 15;
        const float* xm = xmean + b * DIM;
        const float* w  = Wg + j * DIM;
        float s = bg[j];
        for (int d = 0; d < DIM; d++) s = fmaf(xm[d], w[d], s);
        gg[b][j] = 1.f / (1.f + expf(-s));
    }
    __syncthreads();
    for (int idx = t; idx < BATCH * DIM; idx += 256){
        int b = idx >> 8, d = idx & 255;
        const float* w = Wgp + d * 16;
        float s = bgp[d];
#pragma unroll
        for (int j = 0; j < 16; j++) s = fmaf(gg[b][j], w[j], s);
        gproj[idx] = s;
    }
}

// =====================================================================
// per-row: quantile threshold -> masked softmax -> sparse att = p @ V
// one block per (b,h,q) row. Deterministic.
// =====================================================================
__global__ void __launch_bounds__(256) attn_row_kernel(
    const float* __restrict__ scores,
    const float* __restrict__ V,
    float* __restrict__ att)
{
    __shared__ unsigned keys[SEQ];
    __shared__ float pv[SEQ];
    __shared__ unsigned short idxs[SEQ];
    __shared__ int hist[256];
    __shared__ int wsum[8];
    __shared__ float fred[8];
    __shared__ float accbuf[8][64];
    __shared__ int s_bin, s_rem;
    __shared__ float s_slo, s_max, s_sum;

    const int t = threadIdx.x, lane = t & 31, w = t >> 5;
    const int r = blockIdx.x, q = r & (SEQ - 1), bh = r >> 11;

    const float4* row4 = (const float4*)(scores + (size_t)r * SEQ);
    float4 f0 = row4[t], f1 = row4[256 + t];
    float sv[8] = {f0.x, f0.y, f0.z, f0.w, f1.x, f1.y, f1.z, f1.w};

    uint4 kk0, kk1;
    kk0.x = f2k(sv[0]); kk0.y = f2k(sv[1]); kk0.z = f2k(sv[2]); kk0.w = f2k(sv[3]);
    kk1.x = f2k(sv[4]); kk1.y = f2k(sv[5]); kk1.z = f2k(sv[6]); kk1.w = f2k(sv[7]);
    *(uint4*)&keys[4 * t]        = kk0;
    *(uint4*)&keys[1024 + 4 * t] = kk1;

    float lmax = sv[0];
#pragma unroll
    for (int i = 1; i < 8; i++) lmax = fmaxf(lmax, sv[i]);
#pragma unroll
    for (int o = 16; o; o >>= 1)
        lmax = fmaxf(lmax, __shfl_xor_sync(0xffffffffu, lmax, o));
    if (lane == 0) fred[w] = lmax;
    __syncthreads();            // publishes keys + fred
    if (t == 0){
        float m = fred[0];
#pragma unroll
        for (int i = 1; i < 8; i++) m = fmaxf(m, fred[i]);
        s_max = m;
    }

    // ---- radix select: value of rank-205 (205th largest) ----
    unsigned prefix = 0;
    int rem = 205;
#pragma unroll
    for (int shift = 24; shift >= 0; shift -= 8){
        hist[t] = 0;
        __syncthreads();
        unsigned himask = (shift == 24) ? 0u : (0xFFFFFFFFu << (shift + 8));
#pragma unroll
        for (int i = 0; i < 8; i++){
            unsigned key = keys[t + (i << 8)];
            if ((key & himask) == prefix)
                atomicAdd(&hist[(key >> shift) & 0xFFu], 1);
        }
        __syncthreads();
        int u = 255 - t;
        int s = hist[u];
#pragma unroll
        for (int o = 1; o < 32; o <<= 1){
            int n = __shfl_up_sync(0xffffffffu, s, o);
            if (lane >= o) s += n;
        }
        if (lane == 31) wsum[w] = s;
        __syncthreads();
        int off = 0;
#pragma unroll
        for (int i = 0; i < 8; i++) if (i < w) off += wsum[i];
        int pprev = __shfl_up_sync(0xffffffffu, s, 1);
        int nxt = (lane > 0) ? (off + pprev) : off;
        int sfx = off + s;
        if (sfx >= rem && nxt < rem){ s_bin = u; s_rem = rem - nxt; }
        __syncthreads();
        prefix |= ((unsigned)s_bin) << shift;
        rem = s_rem;
    }
    float shi = k2f(prefix);

    // ---- rank-206 value: count >= shi; max < shi ----
    int cge = 0;
    float lmlt = -3.4e38f;
#pragma unroll
    for (int i = 0; i < 8; i++){
        if (sv[i] >= shi) cge++;
        else lmlt = fmaxf(lmlt, sv[i]);
    }
#pragma unroll
    for (int o = 16; o; o >>= 1){
        cge  += __shfl_xor_sync(0xffffffffu, cge, o);
        lmlt  = fmaxf(lmlt, __shfl_xor_sync(0xffffffffu, lmlt, o));
    }
    if (lane == 0){ hist[w] = cge; fred[w] = lmlt; }
    __syncthreads();
    if (t == 0){
        int c = 0; float m = -3.4e38f;
#pragma unroll
        for (int i = 0; i < 8; i++){ c += hist[i]; m = fmaxf(m, fred[i]); }
        s_slo = (c >= 206) ? shi : m;
    }
    __syncthreads();
    float slo = s_slo;
    const float idxf = 0.9f * 2047.0f;   // same arithmetic as passing version
    const float frac = idxf - 1842.0f;
    float thr = slo + frac * (shi - slo);
    float rowmax = s_max;

    // ---- exp + deterministic compaction ----
    float ev[8];
    unsigned kmask = 0;
    int kcnt = 0;
    float lsum = 0.f;
#pragma unroll
    for (int i = 0; i < 8; i++){
        ev[i] = 0.f;
        if (sv[i] >= thr){
            float e = expf(sv[i] - rowmax);
            ev[i] = e; lsum += e;
            kmask |= (1u << i); kcnt++;
        }
    }
    int ps = kcnt;
#pragma unroll
    for (int o = 1; o < 32; o <<= 1){
        int n = __shfl_up_sync(0xffffffffu, ps, o);
        if (lane >= o) ps += n;
    }
    if (lane == 31) wsum[w] = ps;
#pragma unroll
    for (int o = 16; o; o >>= 1)
        lsum += __shfl_xor_sync(0xffffffffu, lsum, o);
    if (lane == 0) fred[w] = lsum;
    __syncthreads();
    int off = 0, tot = 0;
#pragma unroll
    for (int i = 0; i < 8; i++){ if (i < w) off += wsum[i]; tot += wsum[i]; }
    int pos = off + ps - kcnt;
#pragma unroll
    for (int i = 0; i < 8; i++){
        if (kmask & (1u << i)){
            idxs[pos] = (unsigned short)((i < 4) ? (4 * t + i) : (1024 + 4 * t + i - 4));
            pv[pos] = ev[i];
            pos++;
        }
    }
    if (t == 0){
        float ss = 0.f;
#pragma unroll
        for (int i = 0; i < 8; i++) ss += fred[i];
        s_sum = ss;
    }
    __syncthreads();           // publishes pv/idxs/s_sum

    // ---- sparse att: 8 warps gather V rows ----
    const float inv = 1.0f / s_sum;
    const float* Vh = V + (size_t)bh * SEQ * HDIM;
    float a0 = 0.f, a1 = 0.f;
    for (int j = w; j < tot; j += 8){
        float p = pv[j];
        const float* vr = Vh + ((size_t)idxs[j] << 6);
        a0 += p * vr[lane];
        a1 += p * vr[lane + 32];
    }
    accbuf[w][lane]      = a0;
    accbuf[w][lane + 32] = a1;
    __syncthreads();
    if (t < 64){
        float tt = 0.f;
#pragma unroll
        for (int w2 = 0; w2 < 8; w2++) tt += accbuf[w2][t];
        int h = bh & (NHEAD - 1), b = bh >> 2;
        att[((size_t)b * SEQ + q) * DIM + h * HDIM + t] = tt * inv;
    }
}

// =====================================================================
// mixed = g * distill(att) + (1-g) * att ; distill = 16x16 per group
// =====================================================================
__global__ void mix_kernel(const float* __restrict__ att,
    const float* __restrict__ Wd, const float* __restrict__ bd,
    const float* __restrict__ gproj, float* __restrict__ mixed)
{
    __shared__ float arow[DIM];
    __shared__ float wd[256];
    __shared__ float bds[16];
    int m = blockIdx.x;
    int b = m >> 11;
    int t = threadIdx.x;
    arow[t] = att[(size_t)m * DIM + t];
    wd[t] = Wd[t];
    if (t < 16) bds[t] = bd[t];
    __syncthreads();
    int g16 = (t >> 4) << 4;
    int jrow = t & 15;
    float s = bds[jrow];
#pragma unroll
    for (int j = 0; j < 16; j++)
        s = fmaf(arow[g16 + j], wd[jrow * 16 + j], s);
    float g = gproj[b * DIM + t];
    mixed[(size_t)m * DIM + t] = g * s + (1.f - g) * arow[t];
}

// =====================================================================
extern "C" void kernel_launch(void* const* d_in, const int* in_sizes, int n_in,
                              void* d_out, int out_size)
{
    (void)in_sizes; (void)n_in; (void)out_size;
    const float* x   = (const float*)d_in[0];
    const float* Wq  = (const float*)d_in[1];
    const float* bq  = (const float*)d_in[2];
    const float* Wk  = (const float*)d_in[3];
    const float* bk  = (const float*)d_in[4];
    const float* Wv  = (const float*)d_in[5];
    const float* bv  = (const float*)d_in[6];
    const float* Wd  = (const float*)d_in[7];
    const float* bd  = (const float*)d_in[8];
    const float* Wg  = (const float*)d_in[9];
    const float* bg  = (const float*)d_in[10];
    const float* Wgp = (const float*)d_in[11];
    const float* bgp = (const float*)d_in[12];
    const float* Wo  = (const float*)d_in[13];
    const float* bo  = (const float*)d_in[14];
    float* out = (float*)d_out;

    float *pQ, *pK, *pV, *pS, *pAtt, *pMix, *pXm, *pGp, *pMp;
    cudaGetSymbolAddress((void**)&pQ,   g_Q);
    cudaGetSymbolAddress((void**)&pK,   g_K);
    cudaGetSymbolAddress((void**)&pV,   g_V);
    cudaGetSymbolAddress((void**)&pS,   g_scores);
    cudaGetSymbolAddress((void**)&pAtt, g_att);
    cudaGetSymbolAddress((void**)&pMix, g_mixed);
    cudaGetSymbolAddress((void**)&pXm,  g_xmean);
    cudaGetSymbolAddress((void**)&pGp,  g_gproj);
    cudaGetSymbolAddress((void**)&pMp,  g_mpart);

    mean1_kernel<<<dim3(BATCH, 16), 256>>>(x, pMp);
    mean2_kernel<<<BATCH, 256>>>(pMp, pXm);
    gate_kernel<<<1, 256>>>(pXm, Wg, bg, Wgp, bgp, pGp);

    qkv_kernel<<<dim3(DIM / 128, (BATCH * SEQ) / 128, 3), 256>>>(
        x, Wq, bq, Wk, bk, Wv, bv, pQ, pK, pV);

    gemm_kernel<<<dim3(SEQ / 128, SEQ / 128, BATCH * NHEAD), 256>>>(
        pQ, pK, nullptr, pS, HDIM, SEQ, 0.125f,
        (size_t)SEQ * HDIM, (size_t)SEQ * HDIM, (size_t)SEQ * SEQ);

    attn_row_kernel<<<NROWS, 256>>>(pS, pV, pAtt);
    mix_kernel<<<BATCH * SEQ, 256>>>(pAtt, Wd, bd, pGp, pMix);

    gemm_kernel<<<dim3(DIM / 128, (BATCH * SEQ) / 128, 1), 256>>>(
        pMix, Wo, bo, out, DIM, DIM, 1.f, 0, 0, 0);
}

// round 4
// speedup vs baseline: 2.3938x; 1.0293x over previous
#include <cuda_runtime.h>
#include <cuda_bf16.h>
#include <math.h>
#include <stdint.h>

#define BATCH 4
#define SEQ   2048
#define DIM   256
#define NHEAD 4
#define HDIM  64
#define NROWS (BATCH*NHEAD*SEQ)

// ---- scratch (allocation-free: device globals) ----
static __device__ __nv_bfloat16 g_Qh[BATCH*NHEAD*SEQ*HDIM];
static __device__ __nv_bfloat16 g_Qm[BATCH*NHEAD*SEQ*HDIM];
static __device__ __nv_bfloat16 g_Ql[BATCH*NHEAD*SEQ*HDIM];
static __device__ __nv_bfloat16 g_Kh[BATCH*NHEAD*SEQ*HDIM];
static __device__ __nv_bfloat16 g_Km[BATCH*NHEAD*SEQ*HDIM];
static __device__ __nv_bfloat16 g_Kl[BATCH*NHEAD*SEQ*HDIM];
static __device__ float g_V[BATCH*NHEAD*SEQ*HDIM];
static __device__ float g_scores[(size_t)NROWS * SEQ];   // 268 MB
static __device__ float g_att[BATCH*SEQ*DIM];
static __device__ float g_mixed[BATCH*SEQ*DIM];
static __device__ float g_xmean[BATCH*DIM];
static __device__ float g_gproj[BATCH*DIM];
static __device__ float g_mpart[BATCH*16*DIM];

// ---- order-preserving float<->uint key transform ----
__device__ __forceinline__ unsigned f2k(float f){
    unsigned u = __float_as_uint(f);
    return (u & 0x80000000u) ? ~u : (u | 0x80000000u);
}
__device__ __forceinline__ float k2f(unsigned k){
    return (k & 0x80000000u) ? __uint_as_float(k & 0x7fffffffu)
                             : __uint_as_float(~k);
}

// ---- mma.sync helpers (baseline PTX, valid on compute_103) ----
__device__ __forceinline__ uint32_t smem_u32(const void* p){
    uint32_t a;
    asm("{ .reg .u64 t; cvta.to.shared.u64 t, %1; cvt.u32.u64 %0, t; }"
        : "=r"(a) : "l"(p));
    return a;
}
#define SW128(o) ((o) ^ (((o) >> 3) & 0x70))

__device__ __forceinline__ void ldsm_x4(uint32_t addr, uint32_t* r){
    asm volatile("ldmatrix.sync.aligned.m8n8.x4.shared.b16 {%0,%1,%2,%3}, [%4];"
        : "=r"(r[0]), "=r"(r[1]), "=r"(r[2]), "=r"(r[3]) : "r"(addr));
}
__device__ __forceinline__ void ldsm_x2(uint32_t addr, uint32_t* r){
    asm volatile("ldmatrix.sync.aligned.m8n8.x2.shared.b16 {%0,%1}, [%2];"
        : "=r"(r[0]), "=r"(r[1]) : "r"(addr));
}
__device__ __forceinline__ void mma16816(float* c, const uint32_t* a, const uint32_t* b){
    asm volatile("mma.sync.aligned.m16n8k16.row.col.f32.bf16.bf16.f32 "
        "{%0,%1,%2,%3}, {%4,%5,%6,%7}, {%8,%9}, {%0,%1,%2,%3};"
        : "+f"(c[0]), "+f"(c[1]), "+f"(c[2]), "+f"(c[3])
        : "r"(a[0]), "r"(a[1]), "r"(a[2]), "r"(a[3]), "r"(b[0]), "r"(b[1]));
}

#define STILE 16384
#define SMMA_SMEM (6*STILE)

// =====================================================================
// scores = (Q*0.125) @ K^T via 6-pass triple-bf16-split HMMA.
// 128x128 tile per block, 8 warps (2x4), each warp 64x32, K=64.
// smem: 6 tiles [128 rows x 128B], SW128 swizzle, conflict-free ldmatrix.
// =====================================================================
__global__ void __launch_bounds__(256) scores_mma_kernel(
    const __nv_bfloat16* __restrict__ Qh, const __nv_bfloat16* __restrict__ Qm,
    const __nv_bfloat16* __restrict__ Ql, const __nv_bfloat16* __restrict__ Kh,
    const __nv_bfloat16* __restrict__ Km, const __nv_bfloat16* __restrict__ Kl,
    float* __restrict__ S)
{
    extern __shared__ char smem[];
    const int t = threadIdx.x, lane = t & 31, wid = t >> 5;
    const int n0 = blockIdx.x * 128, m0 = blockIdx.y * 128, bh = blockIdx.z;

    // ---- load 6 operand tiles into swizzled smem ----
    const __nv_bfloat16* srcs[6] = {Qh, Qm, Ql, Kh, Km, Kl};
    const int row = t >> 1, half = t & 1;
#pragma unroll
    for (int p = 0; p < 6; p++){
        int br = (p < 3) ? m0 : n0;
        const uint4* src = (const uint4*)(srcs[p] + (((size_t)bh * SEQ) + br + row) * HDIM) + half * 4;
        char* tile = smem + p * STILE;
#pragma unroll
        for (int j = 0; j < 4; j++){
            uint4 v = src[j];
            uint32_t off = row * 128 + (half * 4 + j) * 16;
            *(uint4*)(tile + SW128(off)) = v;
        }
    }
    __syncthreads();

    const uint32_t smem_b = smem_u32(smem);
    const int wm = wid >> 2, wn = wid & 3;      // warp tile: rows wm*64, cols wn*32

    float acc[4][4][4];
#pragma unroll
    for (int i = 0; i < 4; i++)
#pragma unroll
        for (int j = 0; j < 4; j++)
#pragma unroll
            for (int k = 0; k < 4; k++) acc[i][j][k] = 0.f;

    // precompute per-lane ldmatrix address components
    const int a_t = lane >> 3, a_r = lane & 7;
    const int a_rowoff = (a_t & 1) * 8 + a_r;           // within m16 tile
    const int a_coloff = (a_t >> 1) * 16;               // 0 or 16 bytes
    const int b_t = (lane >> 3) & 1, b_r = lane & 7;
    const int b_coloff = b_t * 16;

    // passes grouped by A-split: A=h -> B{h,m,l}; A=m -> B{h,m}; A=l -> B{h}
    const int nb[3] = {3, 2, 1};
#pragma unroll
    for (int ai = 0; ai < 3; ai++){
        const uint32_t abase = smem_b + ai * STILE;
#pragma unroll
        for (int ks = 0; ks < 4; ks++){
            const int kb = ks * 32;
            uint32_t a[4][4];
#pragma unroll
            for (int mi = 0; mi < 4; mi++){
                uint32_t off = (uint32_t)(wm * 64 + mi * 16 + a_rowoff) * 128 + kb + a_coloff;
                ldsm_x4(abase + SW128(off), a[mi]);
            }
#pragma unroll
            for (int bi = 0; bi < 3; bi++){
                if (bi >= nb[ai]) break;
                const uint32_t bbase = smem_b + (3 + bi) * STILE;
                uint32_t b[4][2];
#pragma unroll
                for (int nj = 0; nj < 4; nj++){
                    uint32_t off = (uint32_t)(wn * 32 + nj * 8 + b_r) * 128 + kb + b_coloff;
                    ldsm_x2(bbase + SW128(off), b[nj]);
                }
#pragma unroll
                for (int mi = 0; mi < 4; mi++)
#pragma unroll
                    for (int nj = 0; nj < 4; nj++)
                        mma16816(acc[mi][nj], a[mi], b[nj]);
            }
        }
    }

    // ---- epilogue: fragment (gid, 2*tig) layout -> fp32 scores ----
    const int gid = lane >> 2, tig = lane & 3;
    float* Sb = S + (size_t)bh * SEQ * SEQ;
#pragma unroll
    for (int mi = 0; mi < 4; mi++){
        int r0 = m0 + wm * 64 + mi * 16 + gid;
#pragma unroll
        for (int nj = 0; nj < 4; nj++){
            int c = n0 + wn * 32 + nj * 8 + 2 * tig;
            float2 v0 = make_float2(acc[mi][nj][0], acc[mi][nj][1]);
            float2 v1 = make_float2(acc[mi][nj][2], acc[mi][nj][3]);
            *(float2*)(Sb + (size_t)r0 * SEQ + c)       = v0;
            *(float2*)(Sb + (size_t)(r0 + 8) * SEQ + c) = v1;
        }
    }
}

// =====================================================================
// 128x128 SGEMM tile body: modes:
//  0: fp32 row-major; 1: fp32 scatter [b,h,s,hd]; 2: bf16 triple-split scatter
// =====================================================================
__device__ __forceinline__ void gemm_tile(
    const float* __restrict__ A, const float* __restrict__ B,
    const float* __restrict__ bias, float* __restrict__ C,
    int K, int N, float alpha, float bscale, int m0, int n0, int mode,
    __nv_bfloat16* __restrict__ o1, __nv_bfloat16* __restrict__ o2,
    __nv_bfloat16* __restrict__ o3)
{
    __shared__ float As[32][132];
    __shared__ float Bs[32][132];
    const int tid = threadIdx.x;
    const int tx = tid & 15, ty = tid >> 4;
    const int lm = tid >> 1;
    const int lk4 = tid & 1;

    const float* Ag = A + (size_t)(m0 + lm) * K + lk4 * 4;
    const float* Bg = B + (size_t)(n0 + lm) * K + lk4 * 4;

    float4 pa[4], pb[4];
#pragma unroll
    for (int kk = 0; kk < 4; kk++){
        pa[kk] = *(const float4*)(Ag + kk * 8);
        pb[kk] = *(const float4*)(Bg + kk * 8);
    }

    float acc[8][8];
#pragma unroll
    for (int i = 0; i < 8; i++)
#pragma unroll
        for (int j = 0; j < 8; j++) acc[i][j] = 0.f;

    int k0 = 0;
    for (;;){
        __syncthreads();
#pragma unroll
        for (int kk = 0; kk < 4; kk++){
            int kc = lk4 * 4 + kk * 8;
            As[kc+0][lm] = pa[kk].x; As[kc+1][lm] = pa[kk].y;
            As[kc+2][lm] = pa[kk].z; As[kc+3][lm] = pa[kk].w;
            Bs[kc+0][lm] = pb[kk].x; Bs[kc+1][lm] = pb[kk].y;
            Bs[kc+2][lm] = pb[kk].z; Bs[kc+3][lm] = pb[kk].w;
        }
        __syncthreads();
        k0 += 32;
        if (k0 < K){
#pragma unroll
            for (int kk = 0; kk < 4; kk++){
                pa[kk] = *(const float4*)(Ag + k0 + kk * 8);
                pb[kk] = *(const float4*)(Bg + k0 + kk * 8);
            }
        }
#pragma unroll
        for (int kk = 0; kk < 32; kk++){
            float4 a0 = *(const float4*)&As[kk][ty * 4];
            float4 a1 = *(const float4*)&As[kk][64 + ty * 4];
            float4 b0 = *(const float4*)&Bs[kk][tx * 4];
            float4 b1 = *(const float4*)&Bs[kk][64 + tx * 4];
            float av[8] = {a0.x, a0.y, a0.z, a0.w, a1.x, a1.y, a1.z, a1.w};
            float bv[8] = {b0.x, b0.y, b0.z, b0.w, b1.x, b1.y, b1.z, b1.w};
#pragma unroll
            for (int i = 0; i < 8; i++)
#pragma unroll
                for (int j = 0; j < 8; j++)
                    acc[i][j] = fmaf(av[i], bv[j], acc[i][j]);
        }
        if (k0 >= K) break;
    }

    float bvals[8];
#pragma unroll
    for (int jj = 0; jj < 2; jj++){
        int c = n0 + jj * 64 + tx * 4;
        if (bias){
            float4 bb = *(const float4*)(bias + c);
            bvals[jj*4+0] = bb.x * bscale; bvals[jj*4+1] = bb.y * bscale;
            bvals[jj*4+2] = bb.z * bscale; bvals[jj*4+3] = bb.w * bscale;
        } else {
            bvals[jj*4+0] = bvals[jj*4+1] = bvals[jj*4+2] = bvals[jj*4+3] = 0.f;
        }
    }
#pragma unroll
    for (int ii = 0; ii < 8; ii++){
        int r = m0 + ((ii < 4) ? (ty * 4 + ii) : (64 + ty * 4 + ii - 4));
#pragma unroll
        for (int jj = 0; jj < 2; jj++){
            int c = n0 + jj * 64 + tx * 4;
            float4 v;
            v.x = fmaf(acc[ii][jj*4+0], alpha, bvals[jj*4+0]);
            v.y = fmaf(acc[ii][jj*4+1], alpha, bvals[jj*4+1]);
            v.z = fmaf(acc[ii][jj*4+2], alpha, bvals[jj*4+2]);
            v.w = fmaf(acc[ii][jj*4+3], alpha, bvals[jj*4+3]);
            if (mode == 0){
                *(float4*)(C + (size_t)r * N + c) = v;
            } else if (mode == 1){
                int b = r >> 11, s = r & 2047;
                int h = c >> 6,  hd = c & 63;
                *(float4*)(C + (((size_t)(b * NHEAD + h) * SEQ + s) << 6) + hd) = v;
            } else {
                int b = r >> 11, s = r & 2047;
                int h = c >> 6,  hd = c & 63;
                size_t base = (((size_t)(b * NHEAD + h) * SEQ + s) << 6) + hd;
                float vv[4] = {v.x, v.y, v.z, v.w};
                __nv_bfloat16 hi[4], mi[4], lo[4];
#pragma unroll
                for (int j = 0; j < 4; j++){
                    float f = vv[j];
                    hi[j] = __float2bfloat16(f);
                    float r1 = f - __bfloat162float(hi[j]);
                    mi[j] = __float2bfloat16(r1);
                    float r2 = r1 - __bfloat162float(mi[j]);
                    lo[j] = __float2bfloat16(r2);
                }
                *(__nv_bfloat162*)(o1 + base)     = __nv_bfloat162(hi[0], hi[1]);
                *(__nv_bfloat162*)(o1 + base + 2) = __nv_bfloat162(hi[2], hi[3]);
                *(__nv_bfloat162*)(o2 + base)     = __nv_bfloat162(mi[0], mi[1]);
                *(__nv_bfloat162*)(o2 + base + 2) = __nv_bfloat162(mi[2], mi[3]);
                *(__nv_bfloat162*)(o3 + base)     = __nv_bfloat162(lo[0], lo[1]);
                *(__nv_bfloat162*)(o3 + base + 2) = __nv_bfloat162(lo[2], lo[3]);
            }
        }
    }
}

__global__ void __launch_bounds__(256, 2) qkv_kernel(
    const float* __restrict__ x,
    const float* __restrict__ Wq, const float* __restrict__ bq,
    const float* __restrict__ Wk, const float* __restrict__ bk,
    const float* __restrict__ Wv, const float* __restrict__ bv,
    __nv_bfloat16* Qh, __nv_bfloat16* Qm, __nv_bfloat16* Ql,
    __nv_bfloat16* Kh, __nv_bfloat16* Km, __nv_bfloat16* Kl,
    float* Vp)
{
    int z = blockIdx.z;
    int m0 = blockIdx.y * 128, n0 = blockIdx.x * 128;
    if (z == 0){
        gemm_tile(x, Wq, bq, nullptr, DIM, DIM, 0.125f, 0.125f, m0, n0, 2, Qh, Qm, Ql);
    } else if (z == 1){
        gemm_tile(x, Wk, bk, nullptr, DIM, DIM, 1.f, 1.f, m0, n0, 2, Kh, Km, Kl);
    } else {
        gemm_tile(x, Wv, bv, Vp, DIM, DIM, 1.f, 1.f, m0, n0, 1, nullptr, nullptr, nullptr);
    }
}

__global__ void __launch_bounds__(256, 2) gemm_kernel(
    const float* __restrict__ A, const float* __restrict__ B,
    const float* __restrict__ bias, float* __restrict__ C,
    int K, int N, float alpha)
{
    gemm_tile(A, B, bias, C, K, N, alpha, 1.f, blockIdx.y * 128, blockIdx.x * 128, 0,
              nullptr, nullptr, nullptr);
}

// =====================================================================
// two-stage mean over seq
// =====================================================================
__global__ void mean1_kernel(const float* __restrict__ x, float* __restrict__ part)
{
    int b = blockIdx.x, c = blockIdx.y, t = threadIdx.x;
    const float* p = x + ((size_t)b * SEQ + c * 128) * DIM + t;
    float s = 0.f;
    for (int i = 0; i < 128; i++) s += p[(size_t)i * DIM];
    part[(b * 16 + c) * DIM + t] = s;
}
__global__ void mean2_kernel(const float* __restrict__ part, float* __restrict__ xmean)
{
    int b = blockIdx.x, t = threadIdx.x;
    float s = 0.f;
#pragma unroll
    for (int i = 0; i < 16; i++) s += part[(b * 16 + i) * DIM + t];
    xmean[b * DIM + t] = s * (1.0f / SEQ);
}

__global__ void gate_kernel(const float* __restrict__ xmean,
    const float* __restrict__ Wg, const float* __restrict__ bg,
    const float* __restrict__ Wgp, const float* __restrict__ bgp,
    float* __restrict__ gproj)
{
    __shared__ float gg[BATCH][16];
    int t = threadIdx.x;
    if (t < BATCH * 16){
        int b = t >> 4, j = t & 15;
        const float* xm = xmean + b * DIM;
        const float* w  = Wg + j * DIM;
        float s = bg[j];
        for (int d = 0; d < DIM; d++) s = fmaf(xm[d], w[d], s);
        gg[b][j] = 1.f / (1.f + expf(-s));
    }
    __syncthreads();
    for (int idx = t; idx < BATCH * DIM; idx += 256){
        int b = idx >> 8, d = idx & 255;
        const float* w = Wgp + d * 16;
        float s = bgp[d];
#pragma unroll
        for (int j = 0; j < 16; j++) s = fmaf(gg[b][j], w[j], s);
        gproj[idx] = s;
    }
}

// =====================================================================
// per-row: quantile threshold -> masked softmax -> sparse att = p @ V
// =====================================================================
__global__ void __launch_bounds__(256) attn_row_kernel(
    const float* __restrict__ scores,
    const float* __restrict__ V,
    float* __restrict__ att)
{
    __shared__ unsigned keys[SEQ];
    __shared__ float pv[SEQ];
    __shared__ unsigned short idxs[SEQ];
    __shared__ int hist[256];
    __shared__ int wsum[8];
    __shared__ float fred[8];
    __shared__ float accbuf[8][64];
    __shared__ int s_bin, s_rem;
    __shared__ float s_slo, s_max, s_sum;

    const int t = threadIdx.x, lane = t & 31, w = t >> 5;
    const int r = blockIdx.x, q = r & (SEQ - 1), bh = r >> 11;

    const float4* row4 = (const float4*)(scores + (size_t)r * SEQ);
    float4 f0 = row4[t], f1 = row4[256 + t];
    float sv[8] = {f0.x, f0.y, f0.z, f0.w, f1.x, f1.y, f1.z, f1.w};

    uint4 kk0, kk1;
    kk0.x = f2k(sv[0]); kk0.y = f2k(sv[1]); kk0.z = f2k(sv[2]); kk0.w = f2k(sv[3]);
    kk1.x = f2k(sv[4]); kk1.y = f2k(sv[5]); kk1.z = f2k(sv[6]); kk1.w = f2k(sv[7]);
    *(uint4*)&keys[4 * t]        = kk0;
    *(uint4*)&keys[1024 + 4 * t] = kk1;

    float lmax = sv[0];
#pragma unroll
    for (int i = 1; i < 8; i++) lmax = fmaxf(lmax, sv[i]);
#pragma unroll
    for (int o = 16; o; o >>= 1)
        lmax = fmaxf(lmax, __shfl_xor_sync(0xffffffffu, lmax, o));
    if (lane == 0) fred[w] = lmax;
    __syncthreads();
    if (t == 0){
        float m = fred[0];
#pragma unroll
        for (int i = 1; i < 8; i++) m = fmaxf(m, fred[i]);
        s_max = m;
    }

    unsigned prefix = 0;
    int rem = 205;
#pragma unroll
    for (int shift = 24; shift >= 0; shift -= 8){
        hist[t] = 0;
        __syncthreads();
        unsigned himask = (shift == 24) ? 0u : (0xFFFFFFFFu << (shift + 8));
#pragma unroll
        for (int i = 0; i < 8; i++){
            unsigned key = keys[t + (i << 8)];
            if ((key & himask) == prefix)
                atomicAdd(&hist[(key >> shift) & 0xFFu], 1);
        }
        __syncthreads();
        int u = 255 - t;
        int s = hist[u];
#pragma unroll
        for (int o = 1; o < 32; o <<= 1){
            int n = __shfl_up_sync(0xffffffffu, s, o);
            if (lane >= o) s += n;
        }
        if (lane == 31) wsum[w] = s;
        __syncthreads();
        int off = 0;
#pragma unroll
        for (int i = 0; i < 8; i++) if (i < w) off += wsum[i];
        int pprev = __shfl_up_sync(0xffffffffu, s, 1);
        int nxt = (lane > 0) ? (off + pprev) : off;
        int sfx = off + s;
        if (sfx >= rem && nxt < rem){ s_bin = u; s_rem = rem - nxt; }
        __syncthreads();
        prefix |= ((unsigned)s_bin) << shift;
        rem = s_rem;
    }
    float shi = k2f(prefix);

    int cge = 0;
    float lmlt = -3.4e38f;
#pragma unroll
    for (int i = 0; i < 8; i++){
        if (sv[i] >= shi) cge++;
        else lmlt = fmaxf(lmlt, sv[i]);
    }
#pragma unroll
    for (int o = 16; o; o >>= 1){
        cge  += __shfl_xor_sync(0xffffffffu, cge, o);
        lmlt  = fmaxf(lmlt, __shfl_xor_sync(0xffffffffu, lmlt, o));
    }
    if (lane == 0){ hist[w] = cge; fred[w] = lmlt; }
    __syncthreads();
    if (t == 0){
        int c = 0; float m = -3.4e38f;
#pragma unroll
        for (int i = 0; i < 8; i++){ c += hist[i]; m = fmaxf(m, fred[i]); }
        s_slo = (c >= 206) ? shi : m;
    }
    __syncthreads();
    float slo = s_slo;
    const float idxf = 0.9f * 2047.0f;
    const float frac = idxf - 1842.0f;
    float thr = slo + frac * (shi - slo);
    float rowmax = s_max;

    float ev[8];
    unsigned kmask = 0;
    int kcnt = 0;
    float lsum = 0.f;
#pragma unroll
    for (int i = 0; i < 8; i++){
        ev[i] = 0.f;
        if (sv[i] >= thr){
            float e = expf(sv[i] - rowmax);
            ev[i] = e; lsum += e;
            kmask |= (1u << i); kcnt++;
        }
    }
    int ps = kcnt;
#pragma unroll
    for (int o = 1; o < 32; o <<= 1){
        int n = __shfl_up_sync(0xffffffffu, ps, o);
        if (lane >= o) ps += n;
    }
    if (lane == 31) wsum[w] = ps;
#pragma unroll
    for (int o = 16; o; o >>= 1)
        lsum += __shfl_xor_sync(0xffffffffu, lsum, o);
    if (lane == 0) fred[w] = lsum;
    __syncthreads();
    int off = 0, tot = 0;
#pragma unroll
    for (int i = 0; i < 8; i++){ if (i < w) off += wsum[i]; tot += wsum[i]; }
    int pos = off + ps - kcnt;
#pragma unroll
    for (int i = 0; i < 8; i++){
        if (kmask & (1u << i)){
            idxs[pos] = (unsigned short)((i < 4) ? (4 * t + i) : (1024 + 4 * t + i - 4));
            pv[pos] = ev[i];
            pos++;
        }
    }
    if (t == 0){
        float ss = 0.f;
#pragma unroll
        for (int i = 0; i < 8; i++) ss += fred[i];
        s_sum = ss;
    }
    __syncthreads();

    const float inv = 1.0f / s_sum;
    const float* Vh = V + (size_t)bh * SEQ * HDIM;
    float a0 = 0.f, a1 = 0.f;
    for (int j = w; j < tot; j += 8){
        float p = pv[j];
        const float* vr = Vh + ((size_t)idxs[j] << 6);
        a0 += p * vr[lane];
        a1 += p * vr[lane + 32];
    }
    accbuf[w][lane]      = a0;
    accbuf[w][lane + 32] = a1;
    __syncthreads();
    if (t < 64){
        float tt = 0.f;
#pragma unroll
        for (int w2 = 0; w2 < 8; w2++) tt += accbuf[w2][t];
        int h = bh & (NHEAD - 1), b = bh >> 2;
        att[((size_t)b * SEQ + q) * DIM + h * HDIM + t] = tt * inv;
    }
}

// =====================================================================
__global__ void mix_kernel(const float* __restrict__ att,
    const float* __restrict__ Wd, const float* __restrict__ bd,
    const float* __restrict__ gproj, float* __restrict__ mixed)
{
    __shared__ float arow[DIM];
    __shared__ float wd[256];
    __shared__ float bds[16];
    int m = blockIdx.x;
    int b = m >> 11;
    int t = threadIdx.x;
    arow[t] = att[(size_t)m * DIM + t];
    wd[t] = Wd[t];
    if (t < 16) bds[t] = bd[t];
    __syncthreads();
    int g16 = (t >> 4) << 4;
    int jrow = t & 15;
    float s = bds[jrow];
#pragma unroll
    for (int j = 0; j < 16; j++)
        s = fmaf(arow[g16 + j], wd[jrow * 16 + j], s);
    float g = gproj[b * DIM + t];
    mixed[(size_t)m * DIM + t] = g * s + (1.f - g) * arow[t];
}

// =====================================================================
extern "C" void kernel_launch(void* const* d_in, const int* in_sizes, int n_in,
                              void* d_out, int out_size)
{
    (void)in_sizes; (void)n_in; (void)out_size;
    const float* x   = (const float*)d_in[0];
    const float* Wq  = (const float*)d_in[1];
    const float* bq  = (const float*)d_in[2];
    const float* Wk  = (const float*)d_in[3];
    const float* bk  = (const float*)d_in[4];
    const float* Wv  = (const float*)d_in[5];
    const float* bv  = (const float*)d_in[6];
    const float* Wd  = (const float*)d_in[7];
    const float* bd  = (const float*)d_in[8];
    const float* Wg  = (const float*)d_in[9];
    const float* bg  = (const float*)d_in[10];
    const float* Wgp = (const float*)d_in[11];
    const float* bgp = (const float*)d_in[12];
    const float* Wo  = (const float*)d_in[13];
    const float* bo  = (const float*)d_in[14];
    float* out = (float*)d_out;

    __nv_bfloat16 *pQh, *pQm, *pQl, *pKh, *pKm, *pKl;
    float *pV, *pS, *pAtt, *pMix, *pXm, *pGp, *pMp;
    cudaGetSymbolAddress((void**)&pQh, g_Qh);
    cudaGetSymbolAddress((void**)&pQm, g_Qm);
    cudaGetSymbolAddress((void**)&pQl, g_Ql);
    cudaGetSymbolAddress((void**)&pKh, g_Kh);
    cudaGetSymbolAddress((void**)&pKm, g_Km);
    cudaGetSymbolAddress((void**)&pKl, g_Kl);
    cudaGetSymbolAddress((void**)&pV,   g_V);
    cudaGetSymbolAddress((void**)&pS,   g_scores);
    cudaGetSymbolAddress((void**)&pAtt, g_att);
    cudaGetSymbolAddress((void**)&pMix, g_mixed);
    cudaGetSymbolAddress((void**)&pXm,  g_xmean);
    cudaGetSymbolAddress((void**)&pGp,  g_gproj);
    cudaGetSymbolAddress((void**)&pMp,  g_mpart);

    cudaFuncSetAttribute(scores_mma_kernel,
                         cudaFuncAttributeMaxDynamicSharedMemorySize, SMMA_SMEM);

    mean1_kernel<<<dim3(BATCH, 16), 256>>>(x, pMp);
    mean2_kernel<<<BATCH, 256>>>(pMp, pXm);
    gate_kernel<<<1, 256>>>(pXm, Wg, bg, Wgp, bgp, pGp);

    qkv_kernel<<<dim3(DIM / 128, (BATCH * SEQ) / 128, 3), 256>>>(
        x, Wq, bq, Wk, bk, Wv, bv, pQh, pQm, pQl, pKh, pKm, pKl, pV);

    scores_mma_kernel<<<dim3(SEQ / 128, SEQ / 128, BATCH * NHEAD), 256, SMMA_SMEM>>>(
        pQh, pQm, pQl, pKh, pKm, pKl, pS);

    attn_row_kernel<<<NROWS, 256>>>(pS, pV, pAtt);
    mix_kernel<<<BATCH * SEQ, 256>>>(pAtt, Wd, bd, pGp, pMix);

    gemm_kernel<<<dim3(DIM / 128, (BATCH * SEQ) / 128, 1), 256>>>(
        pMix, Wo, bo, out, DIM, DIM, 1.f);
}

// round 5
// speedup vs baseline: 2.5298x; 1.0568x over previous
#include <cuda_runtime.h>
#include <cuda_bf16.h>
#include <math.h>
#include <stdint.h>

#define BATCH 4
#define SEQ   2048
#define DIM   256
#define NHEAD 4
#define HDIM  64
#define NROWS (BATCH*NHEAD*SEQ)

// ---- scratch (allocation-free: device globals) ----
static __device__ __nv_bfloat16 g_Qh[BATCH*NHEAD*SEQ*HDIM];
static __device__ __nv_bfloat16 g_Qm[BATCH*NHEAD*SEQ*HDIM];
static __device__ __nv_bfloat16 g_Ql[BATCH*NHEAD*SEQ*HDIM];
static __device__ __nv_bfloat16 g_Kh[BATCH*NHEAD*SEQ*HDIM];
static __device__ __nv_bfloat16 g_Km[BATCH*NHEAD*SEQ*HDIM];
static __device__ __nv_bfloat16 g_Kl[BATCH*NHEAD*SEQ*HDIM];
static __device__ float g_Qf[BATCH*NHEAD*SEQ*HDIM];   // fp32 (scaled) for FMA heads
static __device__ float g_Kf[BATCH*NHEAD*SEQ*HDIM];
static __device__ float g_V[BATCH*NHEAD*SEQ*HDIM];
static __device__ float g_scores[(size_t)NROWS * SEQ];   // 268 MB
static __device__ float g_att[BATCH*SEQ*DIM];
static __device__ float g_mixed[BATCH*SEQ*DIM];
static __device__ float g_xmean[BATCH*DIM];
static __device__ float g_gproj[BATCH*DIM];
static __device__ float g_mpart[BATCH*16*DIM];

// ---- order-preserving float<->uint key transform ----
__device__ __forceinline__ unsigned f2k(float f){
    unsigned u = __float_as_uint(f);
    return (u & 0x80000000u) ? ~u : (u | 0x80000000u);
}
__device__ __forceinline__ float k2f(unsigned k){
    return (k & 0x80000000u) ? __uint_as_float(k & 0x7fffffffu)
                             : __uint_as_float(~k);
}

// ---- mma.sync helpers (baseline PTX, valid on compute_103) ----
__device__ __forceinline__ uint32_t smem_u32(const void* p){
    uint32_t a;
    asm("{ .reg .u64 t; cvta.to.shared.u64 t, %1; cvt.u32.u64 %0, t; }"
        : "=r"(a) : "l"(p));
    return a;
}
#define SW128(o) ((o) ^ (((o) >> 3) & 0x70))

__device__ __forceinline__ void ldsm_x4(uint32_t addr, uint32_t* r){
    asm volatile("ldmatrix.sync.aligned.m8n8.x4.shared.b16 {%0,%1,%2,%3}, [%4];"
        : "=r"(r[0]), "=r"(r[1]), "=r"(r[2]), "=r"(r[3]) : "r"(addr));
}
__device__ __forceinline__ void ldsm_x2(uint32_t addr, uint32_t* r){
    asm volatile("ldmatrix.sync.aligned.m8n8.x2.shared.b16 {%0,%1}, [%2];"
        : "=r"(r[0]), "=r"(r[1]) : "r"(addr));
}
__device__ __forceinline__ void mma16816(float* c, const uint32_t* a, const uint32_t* b){
    asm volatile("mma.sync.aligned.m16n8k16.row.col.f32.bf16.bf16.f32 "
        "{%0,%1,%2,%3}, {%4,%5,%6,%7}, {%8,%9}, {%0,%1,%2,%3};"
        : "+f"(c[0]), "+f"(c[1]), "+f"(c[2]), "+f"(c[3])
        : "r"(a[0]), "r"(a[1]), "r"(a[2]), "r"(a[3]), "r"(b[0]), "r"(b[1]));
}

#define STILE 16384
#define SMMA_SMEM (6*STILE)

// =====================================================================
// HMMA path: one 128x128 score tile via 6-pass triple-bf16-split.
// =====================================================================
__device__ void hmma_scores_tile(char* smem,
    const __nv_bfloat16* __restrict__ Qh, const __nv_bfloat16* __restrict__ Qm,
    const __nv_bfloat16* __restrict__ Ql, const __nv_bfloat16* __restrict__ Kh,
    const __nv_bfloat16* __restrict__ Km, const __nv_bfloat16* __restrict__ Kl,
    float* __restrict__ S, int bh, int m0, int n0)
{
    const int t = threadIdx.x, lane = t & 31, wid = t >> 5;

    const __nv_bfloat16* srcs[6] = {Qh, Qm, Ql, Kh, Km, Kl};
    const int row = t >> 1, half = t & 1;
#pragma unroll
    for (int p = 0; p < 6; p++){
        int br = (p < 3) ? m0 : n0;
        const uint4* src = (const uint4*)(srcs[p] + (((size_t)bh * SEQ) + br + row) * HDIM) + half * 4;
        char* tile = smem + p * STILE;
#pragma unroll
        for (int j = 0; j < 4; j++){
            uint4 v = src[j];
            uint32_t off = row * 128 + (half * 4 + j) * 16;
            *(uint4*)(tile + SW128(off)) = v;
        }
    }
    __syncthreads();

    const uint32_t smem_b = smem_u32(smem);
    const int wm = wid >> 2, wn = wid & 3;

    float acc[4][4][4];
#pragma unroll
    for (int i = 0; i < 4; i++)
#pragma unroll
        for (int j = 0; j < 4; j++)
#pragma unroll
            for (int k = 0; k < 4; k++) acc[i][j][k] = 0.f;

    const int a_t = lane >> 3, a_r = lane & 7;
    const int a_rowoff = (a_t & 1) * 8 + a_r;
    const int a_coloff = (a_t >> 1) * 16;
    const int b_r = lane & 7;
    const int b_coloff = ((lane >> 3) & 1) * 16;

    const int nb[3] = {3, 2, 1};
#pragma unroll
    for (int ai = 0; ai < 3; ai++){
        const uint32_t abase = smem_b + ai * STILE;
#pragma unroll
        for (int ks = 0; ks < 4; ks++){
            const int kb = ks * 32;
            uint32_t a[4][4];
#pragma unroll
            for (int mi = 0; mi < 4; mi++){
                uint32_t off = (uint32_t)(wm * 64 + mi * 16 + a_rowoff) * 128 + kb + a_coloff;
                ldsm_x4(abase + SW128(off), a[mi]);
            }
#pragma unroll
            for (int bi = 0; bi < 3; bi++){
                if (bi >= nb[ai]) break;
                const uint32_t bbase = smem_b + (3 + bi) * STILE;
                uint32_t b[4][2];
#pragma unroll
                for (int nj = 0; nj < 4; nj++){
                    uint32_t off = (uint32_t)(wn * 32 + nj * 8 + b_r) * 128 + kb + b_coloff;
                    ldsm_x2(bbase + SW128(off), b[nj]);
                }
#pragma unroll
                for (int mi = 0; mi < 4; mi++)
#pragma unroll
                    for (int nj = 0; nj < 4; nj++)
                        mma16816(acc[mi][nj], a[mi], b[nj]);
            }
        }
    }

    const int gid = lane >> 2, tig = lane & 3;
    float* Sb = S + (size_t)bh * SEQ * SEQ;
#pragma unroll
    for (int mi = 0; mi < 4; mi++){
        int r0 = m0 + wm * 64 + mi * 16 + gid;
#pragma unroll
        for (int nj = 0; nj < 4; nj++){
            int c = n0 + wn * 32 + nj * 8 + 2 * tig;
            float2 v0 = make_float2(acc[mi][nj][0], acc[mi][nj][1]);
            float2 v1 = make_float2(acc[mi][nj][2], acc[mi][nj][3]);
            *(float2*)(Sb + (size_t)r0 * SEQ + c)       = v0;
            *(float2*)(Sb + (size_t)(r0 + 8) * SEQ + c) = v1;
        }
    }
}

// =====================================================================
// FMA path: one 128x128 score tile, fp32, K=64 (dynamic smem).
// =====================================================================
__device__ void fma_scores_tile(char* smem_raw,
    const float* __restrict__ Qf, const float* __restrict__ Kf,
    float* __restrict__ S, int bh, int m0, int n0)
{
    float (*As)[132] = reinterpret_cast<float(*)[132]>(smem_raw);
    float (*Bs)[132] = reinterpret_cast<float(*)[132]>(smem_raw + 32 * 132 * sizeof(float));
    const float* A = Qf + (size_t)bh * SEQ * HDIM;
    const float* B = Kf + (size_t)bh * SEQ * HDIM;
    const int tid = threadIdx.x;
    const int tx = tid & 15, ty = tid >> 4;
    const int lm = tid >> 1, lk4 = tid & 1;

    const float* Ag = A + (size_t)(m0 + lm) * HDIM + lk4 * 4;
    const float* Bg = B + (size_t)(n0 + lm) * HDIM + lk4 * 4;

    float acc[8][8];
#pragma unroll
    for (int i = 0; i < 8; i++)
#pragma unroll
        for (int j = 0; j < 8; j++) acc[i][j] = 0.f;

#pragma unroll
    for (int it = 0; it < 2; it++){
        int k0 = it * 32;
        float4 pa[4], pb[4];
#pragma unroll
        for (int kk = 0; kk < 4; kk++){
            pa[kk] = *(const float4*)(Ag + k0 + kk * 8);
            pb[kk] = *(const float4*)(Bg + k0 + kk * 8);
        }
        __syncthreads();
#pragma unroll
        for (int kk = 0; kk < 4; kk++){
            int kc = lk4 * 4 + kk * 8;
            As[kc+0][lm] = pa[kk].x; As[kc+1][lm] = pa[kk].y;
            As[kc+2][lm] = pa[kk].z; As[kc+3][lm] = pa[kk].w;
            Bs[kc+0][lm] = pb[kk].x; Bs[kc+1][lm] = pb[kk].y;
            Bs[kc+2][lm] = pb[kk].z; Bs[kc+3][lm] = pb[kk].w;
        }
        __syncthreads();
#pragma unroll
        for (int kk = 0; kk < 32; kk++){
            float4 a0 = *(const float4*)&As[kk][ty * 4];
            float4 a1 = *(const float4*)&As[kk][64 + ty * 4];
            float4 b0 = *(const float4*)&Bs[kk][tx * 4];
            float4 b1 = *(const float4*)&Bs[kk][64 + tx * 4];
            float av[8] = {a0.x, a0.y, a0.z, a0.w, a1.x, a1.y, a1.z, a1.w};
            float bv[8] = {b0.x, b0.y, b0.z, b0.w, b1.x, b1.y, b1.z, b1.w};
#pragma unroll
            for (int i = 0; i < 8; i++)
#pragma unroll
                for (int j = 0; j < 8; j++)
                    acc[i][j] = fmaf(av[i], bv[j], acc[i][j]);
        }
    }

    float* Sb = S + (size_t)bh * SEQ * SEQ;
#pragma unroll
    for (int ii = 0; ii < 8; ii++){
        int r = m0 + ((ii < 4) ? (ty * 4 + ii) : (64 + ty * 4 + ii - 4));
#pragma unroll
        for (int jj = 0; jj < 2; jj++){
            int c = n0 + jj * 64 + tx * 4;
            float4 v = make_float4(acc[ii][jj*4+0], acc[ii][jj*4+1],
                                   acc[ii][jj*4+2], acc[ii][jj*4+3]);
            *(float4*)(Sb + (size_t)r * SEQ + c) = v;
        }
    }
}

// =====================================================================
// Hybrid scores kernel: even blockIdx.x -> HMMA (heads 0-7),
// odd -> fp32 FMA (heads 8-15). Types interleave across SMs so both
// pipes run concurrently chip-wide.
// =====================================================================
__global__ void __launch_bounds__(256, 2) scores_hybrid_kernel(
    const __nv_bfloat16* __restrict__ Qh, const __nv_bfloat16* __restrict__ Qm,
    const __nv_bfloat16* __restrict__ Ql, const __nv_bfloat16* __restrict__ Kh,
    const __nv_bfloat16* __restrict__ Km, const __nv_bfloat16* __restrict__ Kl,
    const float* __restrict__ Qf, const float* __restrict__ Kf,
    float* __restrict__ S)
{
    extern __shared__ char smem[];
    const int type = blockIdx.x & 1;
    const int n0 = (blockIdx.x >> 1) * 128;
    const int m0 = blockIdx.y * 128;
    if (type == 0){
        hmma_scores_tile(smem, Qh, Qm, Ql, Kh, Km, Kl, S, blockIdx.z, m0, n0);
    } else {
        fma_scores_tile(smem, Qf, Kf, S, 8 + blockIdx.z, m0, n0);
    }
}

// =====================================================================
// 128x128 SGEMM tile body (static smem): modes:
//  0: fp32 row-major; 1: fp32 scatter [b,h,s,hd];
//  2: QK epilogue — batches 0,1 -> bf16 triple-split, batches 2,3 -> fp32 (C)
// =====================================================================
__device__ __forceinline__ void gemm_tile(
    const float* __restrict__ A, const float* __restrict__ B,
    const float* __restrict__ bias, float* __restrict__ C,
    int K, int N, float alpha, float bscale, int m0, int n0, int mode,
    __nv_bfloat16* __restrict__ o1, __nv_bfloat16* __restrict__ o2,
    __nv_bfloat16* __restrict__ o3)
{
    __shared__ float As[32][132];
    __shared__ float Bs[32][132];
    const int tid = threadIdx.x;
    const int tx = tid & 15, ty = tid >> 4;
    const int lm = tid >> 1;
    const int lk4 = tid & 1;

    const float* Ag = A + (size_t)(m0 + lm) * K + lk4 * 4;
    const float* Bg = B + (size_t)(n0 + lm) * K + lk4 * 4;

    float4 pa[4], pb[4];
#pragma unroll
    for (int kk = 0; kk < 4; kk++){
        pa[kk] = *(const float4*)(Ag + kk * 8);
        pb[kk] = *(const float4*)(Bg + kk * 8);
    }

    float acc[8][8];
#pragma unroll
    for (int i = 0; i < 8; i++)
#pragma unroll
        for (int j = 0; j < 8; j++) acc[i][j] = 0.f;

    int k0 = 0;
    for (;;){
        __syncthreads();
#pragma unroll
        for (int kk = 0; kk < 4; kk++){
            int kc = lk4 * 4 + kk * 8;
            As[kc+0][lm] = pa[kk].x; As[kc+1][lm] = pa[kk].y;
            As[kc+2][lm] = pa[kk].z; As[kc+3][lm] = pa[kk].w;
            Bs[kc+0][lm] = pb[kk].x; Bs[kc+1][lm] = pb[kk].y;
            Bs[kc+2][lm] = pb[kk].z; Bs[kc+3][lm] = pb[kk].w;
        }
        __syncthreads();
        k0 += 32;
        if (k0 < K){
#pragma unroll
            for (int kk = 0; kk < 4; kk++){
                pa[kk] = *(const float4*)(Ag + k0 + kk * 8);
                pb[kk] = *(const float4*)(Bg + k0 + kk * 8);
            }
        }
#pragma unroll
        for (int kk = 0; kk < 32; kk++){
            float4 a0 = *(const float4*)&As[kk][ty * 4];
            float4 a1 = *(const float4*)&As[kk][64 + ty * 4];
            float4 b0 = *(const float4*)&Bs[kk][tx * 4];
            float4 b1 = *(const float4*)&Bs[kk][64 + tx * 4];
            float av[8] = {a0.x, a0.y, a0.z, a0.w, a1.x, a1.y, a1.z, a1.w};
            float bv[8] = {b0.x, b0.y, b0.z, b0.w, b1.x, b1.y, b1.z, b1.w};
#pragma unroll
            for (int i = 0; i < 8; i++)
#pragma unroll
                for (int j = 0; j < 8; j++)
                    acc[i][j] = fmaf(av[i], bv[j], acc[i][j]);
        }
        if (k0 >= K) break;
    }

    float bvals[8];
#pragma unroll
    for (int jj = 0; jj < 2; jj++){
        int c = n0 + jj * 64 + tx * 4;
        if (bias){
            float4 bb = *(const float4*)(bias + c);
            bvals[jj*4+0] = bb.x * bscale; bvals[jj*4+1] = bb.y * bscale;
            bvals[jj*4+2] = bb.z * bscale; bvals[jj*4+3] = bb.w * bscale;
        } else {
            bvals[jj*4+0] = bvals[jj*4+1] = bvals[jj*4+2] = bvals[jj*4+3] = 0.f;
        }
    }
#pragma unroll
    for (int ii = 0; ii < 8; ii++){
        int r = m0 + ((ii < 4) ? (ty * 4 + ii) : (64 + ty * 4 + ii - 4));
#pragma unroll
        for (int jj = 0; jj < 2; jj++){
            int c = n0 + jj * 64 + tx * 4;
            float4 v;
            v.x = fmaf(acc[ii][jj*4+0], alpha, bvals[jj*4+0]);
            v.y = fmaf(acc[ii][jj*4+1], alpha, bvals[jj*4+1]);
            v.z = fmaf(acc[ii][jj*4+2], alpha, bvals[jj*4+2]);
            v.w = fmaf(acc[ii][jj*4+3], alpha, bvals[jj*4+3]);
            if (mode == 0){
                *(float4*)(C + (size_t)r * N + c) = v;
            } else if (mode == 1){
                int b = r >> 11, s = r & 2047;
                int h = c >> 6,  hd = c & 63;
                *(float4*)(C + (((size_t)(b * NHEAD + h) * SEQ + s) << 6) + hd) = v;
            } else {
                int b = r >> 11, s = r & 2047;
                int h = c >> 6,  hd = c & 63;
                size_t base = (((size_t)(b * NHEAD + h) * SEQ + s) << 6) + hd;
                if (b < 2){
                    float vv[4] = {v.x, v.y, v.z, v.w};
                    __nv_bfloat16 hi[4], mi[4], lo[4];
#pragma unroll
                    for (int j = 0; j < 4; j++){
                        float f = vv[j];
                        hi[j] = __float2bfloat16(f);
                        float r1 = f - __bfloat162float(hi[j]);
                        mi[j] = __float2bfloat16(r1);
                        float r2 = r1 - __bfloat162float(mi[j]);
                        lo[j] = __float2bfloat16(r2);
                    }
                    *(__nv_bfloat162*)(o1 + base)     = __nv_bfloat162(hi[0], hi[1]);
                    *(__nv_bfloat162*)(o1 + base + 2) = __nv_bfloat162(hi[2], hi[3]);
                    *(__nv_bfloat162*)(o2 + base)     = __nv_bfloat162(mi[0], mi[1]);
                    *(__nv_bfloat162*)(o2 + base + 2) = __nv_bfloat162(mi[2], mi[3]);
                    *(__nv_bfloat162*)(o3 + base)     = __nv_bfloat162(lo[0], lo[1]);
                    *(__nv_bfloat162*)(o3 + base + 2) = __nv_bfloat162(lo[2], lo[3]);
                } else {
                    *(float4*)(C + base) = v;
                }
            }
        }
    }
}

__global__ void __launch_bounds__(256, 2) qkv_kernel(
    const float* __restrict__ x,
    const float* __restrict__ Wq, const float* __restrict__ bq,
    const float* __restrict__ Wk, const float* __restrict__ bk,
    const float* __restrict__ Wv, const float* __restrict__ bv,
    __nv_bfloat16* Qh, __nv_bfloat16* Qm, __nv_bfloat16* Ql,
    __nv_bfloat16* Kh, __nv_bfloat16* Km, __nv_bfloat16* Kl,
    float* Qf, float* Kf, float* Vp)
{
    int z = blockIdx.z;
    int m0 = blockIdx.y * 128, n0 = blockIdx.x * 128;
    if (z == 0){
        gemm_tile(x, Wq, bq, Qf, DIM, DIM, 0.125f, 0.125f, m0, n0, 2, Qh, Qm, Ql);
    } else if (z == 1){
        gemm_tile(x, Wk, bk, Kf, DIM, DIM, 1.f, 1.f, m0, n0, 2, Kh, Km, Kl);
    } else {
        gemm_tile(x, Wv, bv, Vp, DIM, DIM, 1.f, 1.f, m0, n0, 1, nullptr, nullptr, nullptr);
    }
}

__global__ void __launch_bounds__(256, 2) gemm_kernel(
    const float* __restrict__ A, const float* __restrict__ B,
    const float* __restrict__ bias, float* __restrict__ C,
    int K, int N, float alpha)
{
    gemm_tile(A, B, bias, C, K, N, alpha, 1.f, blockIdx.y * 128, blockIdx.x * 128, 0,
              nullptr, nullptr, nullptr);
}

// =====================================================================
// two-stage mean over seq + gate
// =====================================================================
__global__ void mean1_kernel(const float* __restrict__ x, float* __restrict__ part)
{
    int b = blockIdx.x, c = blockIdx.y, t = threadIdx.x;
    const float* p = x + ((size_t)b * SEQ + c * 128) * DIM + t;
    float s = 0.f;
    for (int i = 0; i < 128; i++) s += p[(size_t)i * DIM];
    part[(b * 16 + c) * DIM + t] = s;
}
__global__ void mean2_kernel(const float* __restrict__ part, float* __restrict__ xmean)
{
    int b = blockIdx.x, t = threadIdx.x;
    float s = 0.f;
#pragma unroll
    for (int i = 0; i < 16; i++) s += part[(b * 16 + i) * DIM + t];
    xmean[b * DIM + t] = s * (1.0f / SEQ);
}

__global__ void gate_kernel(const float* __restrict__ xmean,
    const float* __restrict__ Wg, const float* __restrict__ bg,
    const float* __restrict__ Wgp, const float* __restrict__ bgp,
    float* __restrict__ gproj)
{
    __shared__ float gg[BATCH][16];
    int t = threadIdx.x;
    if (t < BATCH * 16){
        int b = t >> 4, j = t & 15;
        const float* xm = xmean + b * DIM;
        const float* w  = Wg + j * DIM;
        float s = bg[j];
        for (int d = 0; d < DIM; d++) s = fmaf(xm[d], w[d], s);
        gg[b][j] = 1.f / (1.f + expf(-s));
    }
    __syncthreads();
    for (int idx = t; idx < BATCH * DIM; idx += 256){
        int b = idx >> 8, d = idx & 255;
        const float* w = Wgp + d * 16;
        float s = bgp[d];
#pragma unroll
        for (int j = 0; j < 16; j++) s = fmaf(gg[b][j], w[j], s);
        gproj[idx] = s;
    }
}

// =====================================================================
// per-row: quantile threshold -> masked softmax -> sparse att = p @ V
// radix histogram from registers; 4-way unrolled V gather.
// =====================================================================
__global__ void __launch_bounds__(256) attn_row_kernel(
    const float* __restrict__ scores,
    const float* __restrict__ V,
    float* __restrict__ att)
{
    __shared__ float pv[SEQ];
    __shared__ unsigned short idxs[SEQ];
    __shared__ int hist[256];
    __shared__ int wsum[8];
    __shared__ float fred[8];
    __shared__ float accbuf[8][64];
    __shared__ int s_bin, s_rem;
    __shared__ float s_slo, s_max, s_sum;

    const int t = threadIdx.x, lane = t & 31, w = t >> 5;
    const int r = blockIdx.x, q = r & (SEQ - 1), bh = r >> 11;

    const float4* row4 = (const float4*)(scores + (size_t)r * SEQ);
    float4 f0 = row4[t], f1 = row4[256 + t];
    float sv[8] = {f0.x, f0.y, f0.z, f0.w, f1.x, f1.y, f1.z, f1.w};
    unsigned kv[8];
#pragma unroll
    for (int i = 0; i < 8; i++) kv[i] = f2k(sv[i]);

    float lmax = sv[0];
#pragma unroll
    for (int i = 1; i < 8; i++) lmax = fmaxf(lmax, sv[i]);
#pragma unroll
    for (int o = 16; o; o >>= 1)
        lmax = fmaxf(lmax, __shfl_xor_sync(0xffffffffu, lmax, o));
    if (lane == 0) fred[w] = lmax;
    __syncthreads();
    if (t == 0){
        float m = fred[0];
#pragma unroll
        for (int i = 1; i < 8; i++) m = fmaxf(m, fred[i]);
        s_max = m;
    }

    // ---- radix select: value of rank-205 (205th largest) ----
    unsigned prefix = 0;
    int rem = 205;
#pragma unroll
    for (int shift = 24; shift >= 0; shift -= 8){
        hist[t] = 0;
        __syncthreads();
        unsigned himask = (shift == 24) ? 0u : (0xFFFFFFFFu << (shift + 8));
#pragma unroll
        for (int i = 0; i < 8; i++){
            if ((kv[i] & himask) == prefix)
                atomicAdd(&hist[(kv[i] >> shift) & 0xFFu], 1);
        }
        __syncthreads();
        int u = 255 - t;
        int s = hist[u];
#pragma unroll
        for (int o = 1; o < 32; o <<= 1){
            int n = __shfl_up_sync(0xffffffffu, s, o);
            if (lane >= o) s += n;
        }
        if (lane == 31) wsum[w] = s;
        __syncthreads();
        int off = 0;
#pragma unroll
        for (int i = 0; i < 8; i++) if (i < w) off += wsum[i];
        int pprev = __shfl_up_sync(0xffffffffu, s, 1);
        int nxt = (lane > 0) ? (off + pprev) : off;
        int sfx = off + s;
        if (sfx >= rem && nxt < rem){ s_bin = u; s_rem = rem - nxt; }
        __syncthreads();
        prefix |= ((unsigned)s_bin) << shift;
        rem = s_rem;
    }
    float shi = k2f(prefix);

    // ---- rank-206: count >= shi; max < shi ----
    int cge = 0;
    float lmlt = -3.4e38f;
#pragma unroll
    for (int i = 0; i < 8; i++){
        if (sv[i] >= shi) cge++;
        else lmlt = fmaxf(lmlt, sv[i]);
    }
#pragma unroll
    for (int o = 16; o; o >>= 1){
        cge  += __shfl_xor_sync(0xffffffffu, cge, o);
        lmlt  = fmaxf(lmlt, __shfl_xor_sync(0xffffffffu, lmlt, o));
    }
    if (lane == 0){ hist[w] = cge; fred[w] = lmlt; }
    __syncthreads();
    if (t == 0){
        int c = 0; float m = -3.4e38f;
#pragma unroll
        for (int i = 0; i < 8; i++){ c += hist[i]; m = fmaxf(m, fred[i]); }
        s_slo = (c >= 206) ? shi : m;
    }
    __syncthreads();
    float slo = s_slo;
    const float idxf = 0.9f * 2047.0f;
    const float frac = idxf - 1842.0f;
    float thr = slo + frac * (shi - slo);
    float rowmax = s_max;

    // ---- exp + deterministic compaction ----
    float ev[8];
    unsigned kmask = 0;
    int kcnt = 0;
    float lsum = 0.f;
#pragma unroll
    for (int i = 0; i < 8; i++){
        ev[i] = 0.f;
        if (sv[i] >= thr){
            float e = expf(sv[i] - rowmax);
            ev[i] = e; lsum += e;
            kmask |= (1u << i); kcnt++;
        }
    }
    int ps = kcnt;
#pragma unroll
    for (int o = 1; o < 32; o <<= 1){
        int n = __shfl_up_sync(0xffffffffu, ps, o);
        if (lane >= o) ps += n;
    }
    if (lane == 31) wsum[w] = ps;
#pragma unroll
    for (int o = 16; o; o >>= 1)
        lsum += __shfl_xor_sync(0xffffffffu, lsum, o);
    if (lane == 0) fred[w] = lsum;
    __syncthreads();
    int off = 0, tot = 0;
#pragma unroll
    for (int i = 0; i < 8; i++){ if (i < w) off += wsum[i]; tot += wsum[i]; }
    int pos = off + ps - kcnt;
#pragma unroll
    for (int i = 0; i < 8; i++){
        if (kmask & (1u << i)){
            idxs[pos] = (unsigned short)((i < 4) ? (4 * t + i) : (1024 + 4 * t + i - 4));
            pv[pos] = ev[i];
            pos++;
        }
    }
    if (t == 0){
        float ss = 0.f;
#pragma unroll
        for (int i = 0; i < 8; i++) ss += fred[i];
        s_sum = ss;
    }
    __syncthreads();

    // ---- sparse att: 8 warps, 4-way unrolled gather for MLP ----
    const float inv = 1.0f / s_sum;
    const float* Vh = V + (size_t)bh * SEQ * HDIM;
    float a0 = 0.f, a1 = 0.f, a2 = 0.f, a3 = 0.f;
    float a4 = 0.f, a5 = 0.f, a6 = 0.f, a7 = 0.f;
    int j = w;
    for (; j + 24 < tot; j += 32){
        float p0 = pv[j],      p1 = pv[j + 8];
        float p2 = pv[j + 16], p3 = pv[j + 24];
        const float* v0 = Vh + ((size_t)idxs[j]      << 6);
        const float* v1 = Vh + ((size_t)idxs[j + 8]  << 6);
        const float* v2 = Vh + ((size_t)idxs[j + 16] << 6);
        const float* v3 = Vh + ((size_t)idxs[j + 24] << 6);
        a0 += p0 * v0[lane]; a1 += p0 * v0[lane + 32];
        a2 += p1 * v1[lane]; a3 += p1 * v1[lane + 32];
        a4 += p2 * v2[lane]; a5 += p2 * v2[lane + 32];
        a6 += p3 * v3[lane]; a7 += p3 * v3[lane + 32];
    }
    for (; j < tot; j += 8){
        float p = pv[j];
        const float* vr = Vh + ((size_t)idxs[j] << 6);
        a0 += p * vr[lane];
        a1 += p * vr[lane + 32];
    }
    a0 += a2 + a4 + a6;
    a1 += a3 + a5 + a7;
    accbuf[w][lane]      = a0;
    accbuf[w][lane + 32] = a1;
    __syncthreads();
    if (t < 64){
        float tt = 0.f;
#pragma unroll
        for (int w2 = 0; w2 < 8; w2++) tt += accbuf[w2][t];
        int h = bh & (NHEAD - 1), b = bh >> 2;
        att[((size_t)b * SEQ + q) * DIM + h * HDIM + t] = tt * inv;
    }
}

// =====================================================================
__global__ void mix_kernel(const float* __restrict__ att,
    const float* __restrict__ Wd, const float* __restrict__ bd,
    const float* __restrict__ gproj, float* __restrict__ mixed)
{
    __shared__ float arow[DIM];
    __shared__ float wd[256];
    __shared__ float bds[16];
    int m = blockIdx.x;
    int b = m >> 11;
    int t = threadIdx.x;
    arow[t] = att[(size_t)m * DIM + t];
    wd[t] = Wd[t];
    if (t < 16) bds[t] = bd[t];
    __syncthreads();
    int g16 = (t >> 4) << 4;
    int jrow = t & 15;
    float s = bds[jrow];
#pragma unroll
    for (int j = 0; j < 16; j++)
        s = fmaf(arow[g16 + j], wd[jrow * 16 + j], s);
    float g = gproj[b * DIM + t];
    mixed[(size_t)m * DIM + t] = g * s + (1.f - g) * arow[t];
}

// =====================================================================
extern "C" void kernel_launch(void* const* d_in, const int* in_sizes, int n_in,
                              void* d_out, int out_size)
{
    (void)in_sizes; (void)n_in; (void)out_size;
    const float* x   = (const float*)d_in[0];
    const float* Wq  = (const float*)d_in[1];
    const float* bq  = (const float*)d_in[2];
    const float* Wk  = (const float*)d_in[3];
    const float* bk  = (const float*)d_in[4];
    const float* Wv  = (const float*)d_in[5];
    const float* bv  = (const float*)d_in[6];
    const float* Wd  = (const float*)d_in[7];
    const float* bd  = (const float*)d_in[8];
    const float* Wg  = (const float*)d_in[9];
    const float* bg  = (const float*)d_in[10];
    const float* Wgp = (const float*)d_in[11];
    const float* bgp = (const float*)d_in[12];
    const float* Wo  = (const float*)d_in[13];
    const float* bo  = (const float*)d_in[14];
    float* out = (float*)d_out;

    __nv_bfloat16 *pQh, *pQm, *pQl, *pKh, *pKm, *pKl;
    float *pQf, *pKf, *pV, *pS, *pAtt, *pMix, *pXm, *pGp, *pMp;
    cudaGetSymbolAddress((void**)&pQh, g_Qh);
    cudaGetSymbolAddress((void**)&pQm, g_Qm);
    cudaGetSymbolAddress((void**)&pQl, g_Ql);
    cudaGetSymbolAddress((void**)&pKh, g_Kh);
    cudaGetSymbolAddress((void**)&pKm, g_Km);
    cudaGetSymbolAddress((void**)&pKl, g_Kl);
    cudaGetSymbolAddress((void**)&pQf, g_Qf);
    cudaGetSymbolAddress((void**)&pKf, g_Kf);
    cudaGetSymbolAddress((void**)&pV,   g_V);
    cudaGetSymbolAddress((void**)&pS,   g_scores);
    cudaGetSymbolAddress((void**)&pAtt, g_att);
    cudaGetSymbolAddress((void**)&pMix, g_mixed);
    cudaGetSymbolAddress((void**)&pXm,  g_xmean);
    cudaGetSymbolAddress((void**)&pGp,  g_gproj);
    cudaGetSymbolAddress((void**)&pMp,  g_mpart);

    cudaFuncSetAttribute(scores_hybrid_kernel,
                         cudaFuncAttributeMaxDynamicSharedMemorySize, SMMA_SMEM);

    mean1_kernel<<<dim3(BATCH, 16), 256>>>(x, pMp);
    mean2_kernel<<<BATCH, 256>>>(pMp, pXm);
    gate_kernel<<<1, 256>>>(pXm, Wg, bg, Wgp, bgp, pGp);

    qkv_kernel<<<dim3(DIM / 128, (BATCH * SEQ) / 128, 3), 256>>>(
        x, Wq, bq, Wk, bk, Wv, bv, pQh, pQm, pQl, pKh, pKm, pKl, pQf, pKf, pV);

    // grid.x: 32 = 16 n-tiles x 2 interleaved types (even=HMMA heads 0-7, odd=FMA heads 8-15)
    scores_hybrid_kernel<<<dim3(32, 16, 8), 256, SMMA_SMEM>>>(
        pQh, pQm, pQl, pKh, pKm, pKl, pQf, pKf, pS);

    attn_row_kernel<<<NROWS, 256>>>(pS, pV, pAtt);
    mix_kernel<<<BATCH * SEQ, 256>>>(pAtt, Wd, bd, pGp, pMix);

    gemm_kernel<<<dim3(DIM / 128, (BATCH * SEQ) / 128, 1), 256>>>(
        pMix, Wo, bo, out, DIM, DIM, 1.f);
}